// round 1
// baseline (speedup 1.0000x reference)
#include <cuda_runtime.h>
#include <cuda_bf16.h>

// Problem constants (fixed shapes: B=4, L=2048)
#define BQ 4
#define LQ 2048
#define MSEG (LQ - 1)          // 2047 segments per path
#define EPSQ 1e-6f

// Tiling
#define THREADS 256
#define UI 4                   // i-segments per thread (register resident)
#define I_PER_BLOCK (THREADS * UI)              // 1024
#define IT ((MSEG + I_PER_BLOCK - 1) / I_PER_BLOCK)   // 2
#define JT 32
#define J_PER_BLOCK ((MSEG + JT - 1) / JT)      // 64

// Scratch (no cudaMalloc allowed): per-segment {rx,ry,rz,dx,dy,dz}
__device__ float g_segA[BQ * MSEG * 6];
__device__ float g_segB[BQ * MSEG * 6];
__device__ float g_partial[BQ * IT * JT];       // 256 partials

// ---------------------------------------------------------------------------
// Prep: normalize quats -> imaginary-part path points -> segment mid/tangent
// ---------------------------------------------------------------------------
__device__ __forceinline__ void norm_imag(const float4 q, float& x, float& y, float& z) {
    float s = q.x * q.x + q.y * q.y + q.z * q.z + q.w * q.w;
    float rs = rsqrtf(fmaxf(s, 1e-30f));
    float nrm = s * rs;                       // |q|
    float inv = __fdividef(1.0f, nrm + 1e-12f);
    x = q.y * inv; y = q.z * inv; z = q.w * inv;
}

__global__ void prep_kernel(const float* __restrict__ qa, const float* __restrict__ qb) {
    int idx = blockIdx.x * blockDim.x + threadIdx.x;
    if (idx >= BQ * MSEG) return;
    int b = idx / MSEG;
    int i = idx - b * MSEG;
    long base = ((long)b * LQ + i) * 4;

    float4 a0 = *reinterpret_cast<const float4*>(qa + base);
    float4 a1 = *reinterpret_cast<const float4*>(qa + base + 4);
    float4 b0 = *reinterpret_cast<const float4*>(qb + base);
    float4 b1 = *reinterpret_cast<const float4*>(qb + base + 4);

    float p0x, p0y, p0z, p1x, p1y, p1z;
    float* outA = g_segA + (long)idx * 6;
    norm_imag(a0, p0x, p0y, p0z);
    norm_imag(a1, p1x, p1y, p1z);
    outA[0] = (p1x + p0x) * 0.5f;  outA[1] = (p1y + p0y) * 0.5f;  outA[2] = (p1z + p0z) * 0.5f;
    outA[3] = p1x - p0x;           outA[4] = p1y - p0y;           outA[5] = p1z - p0z;

    float* outB = g_segB + (long)idx * 6;
    norm_imag(b0, p0x, p0y, p0z);
    norm_imag(b1, p1x, p1y, p1z);
    outB[0] = (p1x + p0x) * 0.5f;  outB[1] = (p1y + p0y) * 0.5f;  outB[2] = (p1z + p0z) * 0.5f;
    outB[3] = p1x - p0x;           outB[4] = p1y - p0y;           outB[5] = p1z - p0z;
}

// ---------------------------------------------------------------------------
// All-pairs kernel: grid (JT, IT, B). Each thread owns UI i-segments in regs,
// block stages J_PER_BLOCK j-segments in SMEM (broadcast reads).
// ---------------------------------------------------------------------------
__global__ __launch_bounds__(THREADS) void pairs_kernel() {
    __shared__ float sj[J_PER_BLOCK * 6];     // 1.5 KB
    __shared__ float red[THREADS];

    const int b  = blockIdx.z;
    const int it = blockIdx.y;
    const int jt = blockIdx.x;
    const int t  = threadIdx.x;

    const int j0 = jt * J_PER_BLOCK;
    const int jcount = min(J_PER_BLOCK, MSEG - j0);

    // Stage j-segments (coalesced: contiguous floats)
    const float* srcB = g_segB + ((long)b * MSEG + j0) * 6;
    for (int k = t; k < jcount * 6; k += THREADS) sj[k] = srcB[k];
    __syncthreads();

    // Load UI i-segments (strided by THREADS for coalescing); invalid -> zeros
    float ax[UI], ay[UI], az[UI], dax[UI], day[UI], daz[UI];
    const float* srcA = g_segA + (long)b * MSEG * 6;
    #pragma unroll
    for (int u = 0; u < UI; u++) {
        int i = it * I_PER_BLOCK + u * THREADS + t;
        if (i < MSEG) {
            const float* p = srcA + (long)i * 6;
            ax[u] = p[0]; ay[u] = p[1]; az[u] = p[2];
            dax[u] = p[3]; day[u] = p[4]; daz[u] = p[5];
        } else {
            ax[u] = ay[u] = az[u] = 0.f;
            dax[u] = day[u] = daz[u] = 0.f;   // cross=0 -> term contributes 0
        }
    }

    float acc = 0.0f;
    for (int j = 0; j < jcount; j++) {
        const float bx  = sj[j * 6 + 0];
        const float by  = sj[j * 6 + 1];
        const float bz  = sj[j * 6 + 2];
        const float dbx = sj[j * 6 + 3];
        const float dby = sj[j * 6 + 4];
        const float dbz = sj[j * 6 + 5];
        #pragma unroll
        for (int u = 0; u < UI; u++) {
            float rdx = ax[u] - bx;
            float rdy = ay[u] - by;
            float rdz = az[u] - bz;
            // c = dr_a x dr_b
            float cx = day[u] * dbz - daz[u] * dby;
            float cy = daz[u] * dbx - dax[u] * dbz;
            float cz = dax[u] * dby - day[u] * dbx;
            float num = rdx * cx + rdy * cy + rdz * cz;
            float d2  = fmaxf(rdx * rdx + rdy * rdy + rdz * rdz, 1e-24f);
            float rs  = rsqrtf(d2);
            float den = d2 * rs + EPSQ;       // |r_diff| + eps
            acc += __fdividef(num, den * den * den);
        }
    }

    // Deterministic block tree-reduce
    red[t] = acc;
    __syncthreads();
    #pragma unroll
    for (int off = THREADS / 2; off >= 1; off >>= 1) {
        if (t < off) red[t] += red[t + off];
        __syncthreads();
    }
    if (t == 0) g_partial[(b * IT + it) * JT + jt] = red[0];
}

// ---------------------------------------------------------------------------
// Final: combine 64 partials per batch (double), out = mean|S_b| / (4*pi)
// ---------------------------------------------------------------------------
__global__ void final_kernel(float* __restrict__ out) {
    __shared__ double s[BQ * IT * JT];
    int t = threadIdx.x;                       // 256 threads
    s[t] = (double)g_partial[t];
    __syncthreads();
    const int per_b = IT * JT;                 // 64
    #pragma unroll
    for (int off = per_b / 2; off >= 1; off >>= 1) {
        if ((t & (per_b - 1)) < off) s[t] += s[t + off];
        __syncthreads();
    }
    if (t == 0) {
        double tot = 0.0;
        for (int b = 0; b < BQ; b++) tot += fabs(s[b * per_b]);
        out[0] = (float)(tot / ((double)BQ * 4.0 * 3.14159265358979323846));
    }
}

// ---------------------------------------------------------------------------
extern "C" void kernel_launch(void* const* d_in, const int* in_sizes, int n_in,
                              void* d_out, int out_size) {
    const float* qa = (const float*)d_in[0];   // genomic_quats [B,L,4]
    const float* qb = (const float*)d_in[1];   // code_quats    [B,L,4]
    float* out = (float*)d_out;

    int nseg = BQ * MSEG;
    prep_kernel<<<(nseg + 255) / 256, 256>>>(qa, qb);

    dim3 grid(JT, IT, BQ);                     // 256 blocks
    pairs_kernel<<<grid, THREADS>>>();

    final_kernel<<<1, BQ * IT * JT>>>(out);
}

// round 2
// speedup vs baseline: 1.1251x; 1.1251x over previous
#include <cuda_runtime.h>
#include <cuda_bf16.h>

// Fixed shapes: B=4, L=2048
#define BQ 4
#define LQ 2048
#define MSEG (LQ - 1)              // 2047 segments per path
#define EPSQ 1e-6f

#define THREADS 256
#define UI 4                        // i-segments per thread
#define I_PER_BLOCK (THREADS * UI)  // 1024
#define IT 2                        // ceil(2047/1024)
#define JT 32
#define JPB 64                      // j-segments per block tile
#define NBLOCKS (BQ * IT * JT)      // 256

// Scratch (no cudaMalloc allowed)
__device__ float        g_partial[NBLOCKS];
__device__ unsigned int g_count = 0;

__device__ __forceinline__ float3 norm_imag4(float4 q) {
    float s  = q.x * q.x + q.y * q.y + q.z * q.z + q.w * q.w;
    float rs = rsqrtf(fmaxf(s, 1e-30f));
    float nrm = s * rs;                          // |q|
    float inv = __fdividef(1.0f, nrm + 1e-12f);
    return make_float3(q.y * inv, q.z * inv, q.w * inv);
}

__global__ __launch_bounds__(THREADS, 2)
void gauss_linking_fused(const float* __restrict__ qa,
                         const float* __restrict__ qb,
                         float* __restrict__ out) {
    __shared__ float  pA[(I_PER_BLOCK + 1) * 3];   // A path points (12.3 KB)
    __shared__ float  pB[(JPB + 1) * 3];           // B path points
    __shared__ float  sj[JPB * 6];                 // B segment mid+tangent
    __shared__ float  red[THREADS];
    __shared__ double fd[NBLOCKS];                 // final-reduce scratch
    __shared__ int    lastFlag;

    const int b  = blockIdx.z;
    const int it = blockIdx.y;
    const int jt = blockIdx.x;
    const int t  = threadIdx.x;

    // ---- Stage & normalize the A-point tile this block needs ----
    const int i0     = it * I_PER_BLOCK;
    const int segcnt = min(I_PER_BLOCK, MSEG - i0);     // 1024 or 1023
    const int nptsA  = segcnt + 1;
    for (int p = t; p < nptsA; p += THREADS) {
        float4 q = *reinterpret_cast<const float4*>(qa + ((long)(b * LQ + i0 + p)) * 4);
        float3 v = norm_imag4(q);
        pA[p * 3 + 0] = v.x; pA[p * 3 + 1] = v.y; pA[p * 3 + 2] = v.z;
    }

    // ---- Stage & normalize B-point tile, then build segment data ----
    const int j0     = jt * JPB;
    const int jcount = min(JPB, MSEG - j0);             // 64 (63 for last tile)
    if (t <= jcount) {
        float4 q = *reinterpret_cast<const float4*>(qb + ((long)(b * LQ + j0 + t)) * 4);
        float3 v = norm_imag4(q);
        pB[t * 3 + 0] = v.x; pB[t * 3 + 1] = v.y; pB[t * 3 + 2] = v.z;
    }
    __syncthreads();
    if (t < jcount) {
        float x0 = pB[t * 3 + 0], y0 = pB[t * 3 + 1], z0 = pB[t * 3 + 2];
        float x1 = pB[t * 3 + 3], y1 = pB[t * 3 + 4], z1 = pB[t * 3 + 5];
        sj[t * 6 + 0] = (x1 + x0) * 0.5f;
        sj[t * 6 + 1] = (y1 + y0) * 0.5f;
        sj[t * 6 + 2] = (z1 + z0) * 0.5f;
        sj[t * 6 + 3] = x1 - x0;
        sj[t * 6 + 4] = y1 - y0;
        sj[t * 6 + 5] = z1 - z0;
    }
    __syncthreads();

    // ---- Build register-resident i-segment data from pA ----
    float ax[UI], ay[UI], az[UI], dax[UI], day[UI], daz[UI];
    #pragma unroll
    for (int u = 0; u < UI; u++) {
        int i = u * THREADS + t;
        if (i < segcnt) {
            float x0 = pA[i * 3 + 0], y0 = pA[i * 3 + 1], z0 = pA[i * 3 + 2];
            float x1 = pA[i * 3 + 3], y1 = pA[i * 3 + 4], z1 = pA[i * 3 + 5];
            ax[u]  = (x1 + x0) * 0.5f; ay[u]  = (y1 + y0) * 0.5f; az[u]  = (z1 + z0) * 0.5f;
            dax[u] = x1 - x0;          day[u] = y1 - y0;          daz[u] = z1 - z0;
        } else {
            ax[u] = ay[u] = az[u] = 0.f;
            dax[u] = day[u] = daz[u] = 0.f;   // cross = 0 -> contributes 0
        }
    }

    // ---- Main all-pairs loop ----
    float acc = 0.0f;
    for (int j = 0; j < jcount; j++) {
        const float bx  = sj[j * 6 + 0];
        const float by  = sj[j * 6 + 1];
        const float bz  = sj[j * 6 + 2];
        const float dbx = sj[j * 6 + 3];
        const float dby = sj[j * 6 + 4];
        const float dbz = sj[j * 6 + 5];
        #pragma unroll
        for (int u = 0; u < UI; u++) {
            float rdx = ax[u] - bx;
            float rdy = ay[u] - by;
            float rdz = az[u] - bz;
            float cx = day[u] * dbz - daz[u] * dby;
            float cy = daz[u] * dbx - dax[u] * dbz;
            float cz = dax[u] * dby - day[u] * dbx;
            float num = rdx * cx + rdy * cy + rdz * cz;
            float d2  = fmaxf(rdx * rdx + rdy * rdy + rdz * rdz, 1e-24f);
            float rs  = rsqrtf(d2);
            float den = d2 * rs + EPSQ;        // |r_diff| + eps
            acc += __fdividef(num, den * den * den);
        }
    }

    // ---- Deterministic block tree-reduce ----
    red[t] = acc;
    __syncthreads();
    #pragma unroll
    for (int off = THREADS / 2; off >= 1; off >>= 1) {
        if (t < off) red[t] += red[t + off];
        __syncthreads();
    }

    // ---- Last-block-done final reduction (deterministic fixed-order) ----
    if (t == 0) {
        g_partial[(b * IT + it) * JT + jt] = red[0];
        __threadfence();
        unsigned int tk = atomicAdd(&g_count, 1u);
        lastFlag = (tk == NBLOCKS - 1u) ? 1 : 0;
    }
    __syncthreads();

    if (lastFlag) {
        // All other blocks' partials are globally visible (their threadfence
        // preceded the counter increment we observed). Bypass L1 to be safe.
        fd[t] = (double)__ldcg(&g_partial[t]);
        __syncthreads();
        // Tree-reduce within each batch's 64-partial group (fixed order)
        #pragma unroll
        for (int off = 32; off >= 1; off >>= 1) {
            if ((t & 63) < off) fd[t] += fd[t + off];
            __syncthreads();
        }
        if (t == 0) {
            double tot = 0.0;
            #pragma unroll
            for (int bb = 0; bb < BQ; bb++) tot += fabs(fd[bb * 64]);
            out[0] = (float)(tot / ((double)BQ * 4.0 * 3.14159265358979323846));
            g_count = 0;   // reset for next graph replay
        }
    }
}

extern "C" void kernel_launch(void* const* d_in, const int* in_sizes, int n_in,
                              void* d_out, int out_size) {
    const float* qa = (const float*)d_in[0];   // genomic_quats [B,L,4]
    const float* qb = (const float*)d_in[1];   // code_quats    [B,L,4]
    float* out = (float*)d_out;

    dim3 grid(JT, IT, BQ);                     // 256 blocks
    gauss_linking_fused<<<grid, THREADS>>>(qa, qb, out);
}

// round 3
// speedup vs baseline: 1.1344x; 1.0083x over previous
#include <cuda_runtime.h>
#include <cuda_bf16.h>

// Fixed shapes: B=4, L=2048
#define BQ 4
#define LQ 2048
#define MSEG (LQ - 1)              // 2047 segments per path
#define EPSQ 1e-6f

#define THREADS 256
#define UI 4                        // i-segments per thread
#define I_PER_BLOCK (THREADS * UI)  // 1024
#define IT 2                        // ceil(2047/1024)
#define JT 32
#define JPB 64                      // j-segments per block tile
#define NBLOCKS (BQ * IT * JT)      // 256

// Scratch (no cudaMalloc allowed)
__device__ float        g_partial[NBLOCKS];
__device__ unsigned int g_count = 0;

__device__ __forceinline__ float3 norm_imag4(float4 q) {
    float s  = q.x * q.x + q.y * q.y + q.z * q.z + q.w * q.w;
    float rs = rsqrtf(fmaxf(s, 1e-30f));
    float nrm = s * rs;                          // |q|
    float inv = __fdividef(1.0f, nrm + 1e-12f);
    return make_float3(q.y * inv, q.z * inv, q.w * inv);
}

__global__ __launch_bounds__(THREADS, 2)
void gauss_linking_fused(const float* __restrict__ qa,
                         const float* __restrict__ qb,
                         float* __restrict__ out) {
    __shared__ float  pA[(I_PER_BLOCK + 1) * 3];   // A path points (12.3 KB)
    __shared__ float  pB[(JPB + 1) * 3];           // B path points
    __shared__ float  sj[JPB * 6];                 // B segment mid+tangent
    __shared__ float  red[THREADS];
    __shared__ double fd[NBLOCKS];                 // final-reduce scratch
    __shared__ int    lastFlag;

    const int b  = blockIdx.z;
    const int it = blockIdx.y;
    const int jt = blockIdx.x;
    const int t  = threadIdx.x;

    // ---- Stage & normalize the A-point tile this block needs ----
    const int i0     = it * I_PER_BLOCK;
    const int segcnt = min(I_PER_BLOCK, MSEG - i0);     // 1024 or 1023
    const int nptsA  = segcnt + 1;
    for (int p = t; p < nptsA; p += THREADS) {
        float4 q = *reinterpret_cast<const float4*>(qa + ((long)(b * LQ + i0 + p)) * 4);
        float3 v = norm_imag4(q);
        pA[p * 3 + 0] = v.x; pA[p * 3 + 1] = v.y; pA[p * 3 + 2] = v.z;
    }

    // ---- Stage & normalize B-point tile, then build segment data ----
    const int j0     = jt * JPB;
    const int jcount = min(JPB, MSEG - j0);             // 64 (63 for last tile)
    if (t <= jcount) {
        float4 q = *reinterpret_cast<const float4*>(qb + ((long)(b * LQ + j0 + t)) * 4);
        float3 v = norm_imag4(q);
        pB[t * 3 + 0] = v.x; pB[t * 3 + 1] = v.y; pB[t * 3 + 2] = v.z;
    }
    __syncthreads();
    if (t < jcount) {
        float x0 = pB[t * 3 + 0], y0 = pB[t * 3 + 1], z0 = pB[t * 3 + 2];
        float x1 = pB[t * 3 + 3], y1 = pB[t * 3 + 4], z1 = pB[t * 3 + 5];
        sj[t * 6 + 0] = (x1 + x0) * 0.5f;
        sj[t * 6 + 1] = (y1 + y0) * 0.5f;
        sj[t * 6 + 2] = (z1 + z0) * 0.5f;
        sj[t * 6 + 3] = x1 - x0;
        sj[t * 6 + 4] = y1 - y0;
        sj[t * 6 + 5] = z1 - z0;
    }
    __syncthreads();

    // ---- Build register-resident i-segment data from pA ----
    float ax[UI], ay[UI], az[UI], dax[UI], day[UI], daz[UI];
    #pragma unroll
    for (int u = 0; u < UI; u++) {
        int i = u * THREADS + t;
        if (i < segcnt) {
            float x0 = pA[i * 3 + 0], y0 = pA[i * 3 + 1], z0 = pA[i * 3 + 2];
            float x1 = pA[i * 3 + 3], y1 = pA[i * 3 + 4], z1 = pA[i * 3 + 5];
            ax[u]  = (x1 + x0) * 0.5f; ay[u]  = (y1 + y0) * 0.5f; az[u]  = (z1 + z0) * 0.5f;
            dax[u] = x1 - x0;          day[u] = y1 - y0;          daz[u] = z1 - z0;
        } else {
            ax[u] = ay[u] = az[u] = 0.f;
            dax[u] = day[u] = daz[u] = 0.f;   // cross = 0 -> contributes 0
        }
    }

    // ---- Main all-pairs loop ----
    float acc = 0.0f;
    for (int j = 0; j < jcount; j++) {
        const float bx  = sj[j * 6 + 0];
        const float by  = sj[j * 6 + 1];
        const float bz  = sj[j * 6 + 2];
        const float dbx = sj[j * 6 + 3];
        const float dby = sj[j * 6 + 4];
        const float dbz = sj[j * 6 + 5];
        #pragma unroll
        for (int u = 0; u < UI; u++) {
            float rdx = ax[u] - bx;
            float rdy = ay[u] - by;
            float rdz = az[u] - bz;
            float cx = day[u] * dbz - daz[u] * dby;
            float cy = daz[u] * dbx - dax[u] * dbz;
            float cz = dax[u] * dby - day[u] * dbx;
            float num = rdx * cx + rdy * cy + rdz * cz;
            float d2  = fmaxf(rdx * rdx + rdy * rdy + rdz * rdz, 1e-24f);
            float rs  = rsqrtf(d2);
            float den = d2 * rs + EPSQ;        // |r_diff| + eps
            acc += __fdividef(num, den * den * den);
        }
    }

    // ---- Deterministic block tree-reduce ----
    red[t] = acc;
    __syncthreads();
    #pragma unroll
    for (int off = THREADS / 2; off >= 1; off >>= 1) {
        if (t < off) red[t] += red[t + off];
        __syncthreads();
    }

    // ---- Last-block-done final reduction (deterministic fixed-order) ----
    if (t == 0) {
        g_partial[(b * IT + it) * JT + jt] = red[0];
        __threadfence();
        unsigned int tk = atomicAdd(&g_count, 1u);
        lastFlag = (tk == NBLOCKS - 1u) ? 1 : 0;
    }
    __syncthreads();

    if (lastFlag) {
        // All other blocks' partials are globally visible (their threadfence
        // preceded the counter increment we observed). Bypass L1 to be safe.
        fd[t] = (double)__ldcg(&g_partial[t]);
        __syncthreads();
        // Tree-reduce within each batch's 64-partial group (fixed order)
        #pragma unroll
        for (int off = 32; off >= 1; off >>= 1) {
            if ((t & 63) < off) fd[t] += fd[t + off];
            __syncthreads();
        }
        if (t == 0) {
            double tot = 0.0;
            #pragma unroll
            for (int bb = 0; bb < BQ; bb++) tot += fabs(fd[bb * 64]);
            out[0] = (float)(tot / ((double)BQ * 4.0 * 3.14159265358979323846));
            g_count = 0;   // reset for next graph replay
        }
    }
}

extern "C" void kernel_launch(void* const* d_in, const int* in_sizes, int n_in,
                              void* d_out, int out_size) {
    const float* qa = (const float*)d_in[0];   // genomic_quats [B,L,4]
    const float* qb = (const float*)d_in[1];   // code_quats    [B,L,4]
    float* out = (float*)d_out;

    dim3 grid(JT, IT, BQ);                     // 256 blocks
    gauss_linking_fused<<<grid, THREADS>>>(qa, qb, out);
}